// round 2
// baseline (speedup 1.0000x reference)
#include <cuda_runtime.h>
#include <math.h>

// Problem constants
#define Bc   4
#define Sc   1024
#define HIDc 1024
#define Hc   16
#define Dc   64

// Scratch for Q, K, V in [B,H,S,D] layout (16 MB each)
__device__ float g_q[Bc * Hc * Sc * Dc];
__device__ float g_k[Bc * Hc * Sc * Dc];
__device__ float g_v[Bc * Hc * Sc * Dc];

// ---------------------------------------------------------------------------
// Kernel A: projection GEMM  C = X @ W + bias, scattered to [B,H,S,D]
// X: [4096,1024] row-major, W: [1024(in),1024(out)] row-major.
// BM=BN=128, BK=16, 256 threads, 8x8 micro-tiles.
// ---------------------------------------------------------------------------
__global__ __launch_bounds__(256) void gemm_proj(const float* __restrict__ X,
                                                 const float* __restrict__ W,
                                                 const float* __restrict__ bias,
                                                 int which)
{
    __shared__ float As[16][132];   // transposed A tile: As[k][m]
    __shared__ float Bs[16][132];   // Bs[k][n]
    float* outp = (which == 0) ? g_q : (which == 1) ? g_k : g_v;

    const int tid = threadIdx.x;
    const int m0  = blockIdx.y * 128;
    const int n0  = blockIdx.x * 128;
    const int ty  = tid >> 4;     // 0..15
    const int tx  = tid & 15;     // 0..15

    float acc[8][8];
#pragma unroll
    for (int i = 0; i < 8; i++)
#pragma unroll
        for (int j = 0; j < 8; j++) acc[i][j] = 0.f;

    for (int k0 = 0; k0 < 1024; k0 += 16) {
        // Load A tile (128 rows x 16 k), store transposed
#pragma unroll
        for (int i = 0; i < 2; i++) {
            int f   = tid + i * 256;          // 0..511 float4s
            int row = f >> 2;
            int kc  = (f & 3) << 2;
            float4 va = *(const float4*)(X + (size_t)(m0 + row) * 1024 + k0 + kc);
            As[kc + 0][row] = va.x;
            As[kc + 1][row] = va.y;
            As[kc + 2][row] = va.z;
            As[kc + 3][row] = va.w;
        }
        // Load B tile (16 k x 128 n)
#pragma unroll
        for (int i = 0; i < 2; i++) {
            int f  = tid + i * 256;
            int kr = f >> 5;
            int nc = (f & 31) << 2;
            *(float4*)&Bs[kr][nc] =
                *(const float4*)(W + (size_t)(k0 + kr) * 1024 + n0 + nc);
        }
        __syncthreads();

#pragma unroll
        for (int kk = 0; kk < 16; kk++) {
            float a[8], b[8];
            *(float4*)&a[0] = *(const float4*)&As[kk][ty * 8];
            *(float4*)&a[4] = *(const float4*)&As[kk][ty * 8 + 4];
            *(float4*)&b[0] = *(const float4*)&Bs[kk][tx * 8];
            *(float4*)&b[4] = *(const float4*)&Bs[kk][tx * 8 + 4];
#pragma unroll
            for (int i = 0; i < 8; i++)
#pragma unroll
                for (int j = 0; j < 8; j++)
                    acc[i][j] += a[i] * b[j];
        }
        __syncthreads();
    }

    // Epilogue: add bias, scatter to [B,H,S,D]
#pragma unroll
    for (int i = 0; i < 8; i++) {
        int m = m0 + ty * 8 + i;
        int b = m >> 10;
        int s = m & 1023;
#pragma unroll
        for (int j = 0; j < 8; j++) {
            int n = n0 + tx * 8 + j;
            int h = n >> 6;
            int d = n & 63;
            outp[(((size_t)(b * Hc + h)) * Sc + s) * Dc + d] = acc[i][j] + bias[n];
        }
    }
}

// ---------------------------------------------------------------------------
// Kernel B: fused attention (streaming, no-max masked softmax)
// Block = one (b,h) pair and a 64-row query tile. 256 threads.
// Dynamic smem layout (floats):
// ---------------------------------------------------------------------------
#define QOFF  0                     // 64 x 65
#define KOFF  4160                  // 64 x 65
#define VOFF  8320                  // 64 x 68 (float4-aligned rows)
#define EOFF  12672                 // 127 x 65 (diagonal band of dist_emb)
#define POFF  20927                 // 64 x 65 (probabilities)
#define DNOFF 25087                 // 64 denominators
#define SKOFF 25151                 // 64 skim-mask floats
#define AMOFF 25215                 // 64 attention-mask floats
#define SMEMF 25280
#define ATTN_SMEM_BYTES (SMEMF * 4) // 101120 B

__global__ __launch_bounds__(256) void attn_kernel(const float* __restrict__ attn_mask,
                                                   const int*   __restrict__ skim,
                                                   const float* __restrict__ dist_emb,
                                                   float*       __restrict__ out)
{
    extern __shared__ float smf[];
    const int tid = threadIdx.x;
    const int l0  = blockIdx.x * 64;
    const int bh  = blockIdx.y;
    const int b   = bh >> 4;
    const int h   = bh & 15;
    const int ty  = tid >> 4;
    const int tx  = tid & 15;

    const float* q = g_q + (size_t)bh * Sc * Dc;
    const float* k = g_k + (size_t)bh * Sc * Dc;
    const float* v = g_v + (size_t)bh * Sc * Dc;

    // Load Q tile (64x64)
#pragma unroll
    for (int i = 0; i < 4; i++) {
        int f   = tid + i * 256;       // 0..1023 float4s
        int row = f >> 4;
        int c4  = (f & 15) << 2;
        float4 val = *(const float4*)(q + (size_t)(l0 + row) * 64 + c4);
        smf[QOFF + row * 65 + c4 + 0] = val.x;
        smf[QOFF + row * 65 + c4 + 1] = val.y;
        smf[QOFF + row * 65 + c4 + 2] = val.z;
        smf[QOFF + row * 65 + c4 + 3] = val.w;
    }
    if (tid < 64) smf[DNOFF + tid] = 0.f;

    float acc[4][4];
#pragma unroll
    for (int i = 0; i < 4; i++)
#pragma unroll
        for (int j = 0; j < 4; j++) acc[i][j] = 0.f;

    for (int r0 = 0; r0 < Sc; r0 += 64) {
        __syncthreads();   // prior PV done before we overwrite tiles

        // Load K and V chunks (64x64 each)
#pragma unroll
        for (int i = 0; i < 4; i++) {
            int f   = tid + i * 256;
            int row = f >> 4;
            int c4  = (f & 15) << 2;
            float4 kv = *(const float4*)(k + (size_t)(r0 + row) * 64 + c4);
            smf[KOFF + row * 65 + c4 + 0] = kv.x;
            smf[KOFF + row * 65 + c4 + 1] = kv.y;
            smf[KOFF + row * 65 + c4 + 2] = kv.z;
            smf[KOFF + row * 65 + c4 + 3] = kv.w;
            float4 vv = *(const float4*)(v + (size_t)(r0 + row) * 64 + c4);
            *(float4*)&smf[VOFF + row * 68 + c4] = vv;
        }
        // Load dist_emb diagonal band: rows (l - r + 1023) for this tile pair
        // -> dist_emb rows [l0-r0+960 .. l0-r0+1086], 127 rows of 64 floats.
        {
            int ebase = l0 - r0 + 960;   // always in [0, 1920]
#pragma unroll
            for (int i = 0; i < 8; i++) {
                int f = tid + i * 256;   // need 127*16 = 2032 float4s
                if (f < 2032) {
                    int row = f >> 4;
                    int c4  = (f & 15) << 2;
                    float4 ev = *(const float4*)(dist_emb + (size_t)(ebase + row) * 64 + c4);
                    smf[EOFF + row * 65 + c4 + 0] = ev.x;
                    smf[EOFF + row * 65 + c4 + 1] = ev.y;
                    smf[EOFF + row * 65 + c4 + 2] = ev.z;
                    smf[EOFF + row * 65 + c4 + 3] = ev.w;
                }
            }
        }
        if (tid < 64) {
            smf[AMOFF + tid] = attn_mask[b * Sc + r0 + tid];
            smf[SKOFF + tid] = (float)skim[b * Sc + r0 + tid];
        }
        __syncthreads();

        // ---- Scores: s[li][ri] = sum_d Q[li][d] * (K[ri][d] + E[li-ri+63][d])
        float s4[4][4];
#pragma unroll
        for (int i = 0; i < 4; i++)
#pragma unroll
            for (int j = 0; j < 4; j++) s4[i][j] = 0.f;

        const int   jb   = ((ty - tx) << 2) + 63;       // diag index at il=ir=0
        const float* Qrow = &smf[QOFF + (ty * 4) * 65];
        const float* Krow = &smf[KOFF + (tx * 4) * 65];
        const float* Erow = &smf[EOFF + (jb - 3) * 65]; // jb-3 in [0,120]

#pragma unroll 4
        for (int d = 0; d < 64; d++) {
            float qv[4], kv[4], ev[7];
#pragma unroll
            for (int i = 0; i < 4; i++) qv[i] = Qrow[i * 65 + d];
#pragma unroll
            for (int i = 0; i < 4; i++) kv[i] = Krow[i * 65 + d];
#pragma unroll
            for (int t = 0; t < 7; t++) ev[t] = Erow[t * 65 + d];
#pragma unroll
            for (int il = 0; il < 4; il++)
#pragma unroll
                for (int ir = 0; ir < 4; ir++)
                    s4[il][ir] += qv[il] * (kv[ir] + ev[il - ir + 3]);
        }

        // ---- probs = exp(s/8 + attn_mask) * skim_mask ; accumulate denominators
        float rowsum[4];
#pragma unroll
        for (int il = 0; il < 4; il++) {
            rowsum[il] = 0.f;
#pragma unroll
            for (int ir = 0; ir < 4; ir++) {
                float p = __expf(s4[il][ir] * 0.125f + smf[AMOFF + tx * 4 + ir])
                          * smf[SKOFF + tx * 4 + ir];
                smf[POFF + (ty * 4 + il) * 65 + tx * 4 + ir] = p;
                rowsum[il] += p;
            }
        }
        // reduce rowsum across the 16 tx lanes (xor stays inside 16-lane group)
#pragma unroll
        for (int il = 0; il < 4; il++) {
            float rs = rowsum[il];
            rs += __shfl_xor_sync(0xffffffffu, rs, 1);
            rs += __shfl_xor_sync(0xffffffffu, rs, 2);
            rs += __shfl_xor_sync(0xffffffffu, rs, 4);
            rs += __shfl_xor_sync(0xffffffffu, rs, 8);
            if (tx == 0) smf[DNOFF + ty * 4 + il] += rs;
        }
        __syncthreads();

        // ---- PV accumulate: acc[li][dd] += sum_rr P[li][rr] * V[rr][dd]
        const float* Prow = &smf[POFF + (ty * 4) * 65];
#pragma unroll 4
        for (int rr = 0; rr < 64; rr++) {
            float pv[4];
#pragma unroll
            for (int il = 0; il < 4; il++) pv[il] = Prow[il * 65 + rr];
            float4 vv = *(const float4*)&smf[VOFF + rr * 68 + tx * 4];
            float vvr[4] = {vv.x, vv.y, vv.z, vv.w};
#pragma unroll
            for (int il = 0; il < 4; il++)
#pragma unroll
                for (int id = 0; id < 4; id++)
                    acc[il][id] += pv[il] * vvr[id];
        }
    }
    __syncthreads();

    // ---- write out: out[b, l, h*64 + d] = acc / (eps + denom)
#pragma unroll
    for (int il = 0; il < 4; il++) {
        int l = l0 + ty * 4 + il;
        float dinv = 1.f / (1e-8f + smf[DNOFF + ty * 4 + il]);
#pragma unroll
        for (int id = 0; id < 4; id++) {
            out[((size_t)(b * Sc + l)) * HIDc + h * 64 + tx * 4 + id] =
                acc[il][id] * dinv;
        }
    }
}

// ---------------------------------------------------------------------------
extern "C" void kernel_launch(void* const* d_in, const int* in_sizes, int n_in,
                              void* d_out, int out_size)
{
    const float* hidden = (const float*)d_in[0];
    const float* amask  = (const float*)d_in[1];
    const int*   skim   = (const int*)  d_in[2];
    const float* Wq     = (const float*)d_in[3];
    const float* bq     = (const float*)d_in[4];
    const float* Wk     = (const float*)d_in[5];
    const float* bk     = (const float*)d_in[6];
    const float* Wv     = (const float*)d_in[7];
    const float* bv     = (const float*)d_in[8];
    const float* demb   = (const float*)d_in[9];
    float* out = (float*)d_out;

    dim3 ggrid(8, 32);   // N/128, M/128
    gemm_proj<<<ggrid, 256>>>(hidden, Wq, bq, 0);
    gemm_proj<<<ggrid, 256>>>(hidden, Wk, bk, 1);
    gemm_proj<<<ggrid, 256>>>(hidden, Wv, bv, 2);

    cudaFuncSetAttribute(attn_kernel,
                         cudaFuncAttributeMaxDynamicSharedMemorySize,
                         ATTN_SMEM_BYTES);
    dim3 agrid(Sc / 64, Bc * Hc);
    attn_kernel<<<agrid, 256, ATTN_SMEM_BYTES>>>(amask, skim, demb, out);
}

// round 3
// speedup vs baseline: 1.0002x; 1.0002x over previous
#include <cuda_runtime.h>
#include <math.h>

// Problem constants
#define Bc   4
#define Sc   1024
#define HIDc 1024
#define Hc   16
#define Dc   64

// Scratch for Q, K, V in [B,H,S,D] layout (16 MB each)
__device__ float g_q[Bc * Hc * Sc * Dc];
__device__ float g_k[Bc * Hc * Sc * Dc];
__device__ float g_v[Bc * Hc * Sc * Dc];

// ---------------------------------------------------------------------------
// f32x2 packed helpers
// ---------------------------------------------------------------------------
typedef unsigned long long ull;

__device__ __forceinline__ ull pk2(float lo, float hi) {
    ull r;
    asm("mov.b64 %0, {%1, %2};" : "=l"(r) : "f"(lo), "f"(hi));
    return r;
}
__device__ __forceinline__ void upk2(float& lo, float& hi, ull v) {
    asm("mov.b64 {%0, %1}, %2;" : "=f"(lo), "=f"(hi) : "l"(v));
}
__device__ __forceinline__ void fma2(ull& d, ull a, ull b) {
    asm("fma.rn.f32x2 %0, %1, %2, %0;" : "+l"(d) : "l"(a), "l"(b));
}

// ---------------------------------------------------------------------------
// Kernel A: projection GEMM  C = X @ W + bias, scattered to [B,H,S,D]
// f32x2 inner loop: acc pairs packed along M.
// ---------------------------------------------------------------------------
__global__ __launch_bounds__(256) void gemm_proj(const float* __restrict__ X,
                                                 const float* __restrict__ W,
                                                 const float* __restrict__ bias,
                                                 int which)
{
    __shared__ float As[16][132];   // transposed A tile: As[k][m]
    __shared__ float Bs[16][132];   // Bs[k][n]
    float* outp = (which == 0) ? g_q : (which == 1) ? g_k : g_v;

    const int tid = threadIdx.x;
    const int m0  = blockIdx.y * 128;
    const int n0  = blockIdx.x * 128;
    const int ty  = tid >> 4;     // 0..15
    const int tx  = tid & 15;     // 0..15

    ull acc2[4][8];               // pairs along m: (m=2*i2, m=2*i2+1)
#pragma unroll
    for (int i = 0; i < 4; i++)
#pragma unroll
        for (int j = 0; j < 8; j++) acc2[i][j] = 0ull;

    for (int k0 = 0; k0 < 1024; k0 += 16) {
#pragma unroll
        for (int i = 0; i < 2; i++) {
            int f   = tid + i * 256;
            int row = f >> 2;
            int kc  = (f & 3) << 2;
            float4 va = *(const float4*)(X + (size_t)(m0 + row) * 1024 + k0 + kc);
            As[kc + 0][row] = va.x;
            As[kc + 1][row] = va.y;
            As[kc + 2][row] = va.z;
            As[kc + 3][row] = va.w;
        }
#pragma unroll
        for (int i = 0; i < 2; i++) {
            int f  = tid + i * 256;
            int kr = f >> 5;
            int nc = (f & 31) << 2;
            *(float4*)&Bs[kr][nc] =
                *(const float4*)(W + (size_t)(k0 + kr) * 1024 + n0 + nc);
        }
        __syncthreads();

#pragma unroll
        for (int kk = 0; kk < 16; kk++) {
            ull a2[4];
#pragma unroll
            for (int i2 = 0; i2 < 4; i2++)
                a2[i2] = *(const ull*)&As[kk][ty * 8 + i2 * 2];
            float bn[8];
            *(float4*)&bn[0] = *(const float4*)&Bs[kk][tx * 8];
            *(float4*)&bn[4] = *(const float4*)&Bs[kk][tx * 8 + 4];
#pragma unroll
            for (int j = 0; j < 8; j++) {
                ull b2 = pk2(bn[j], bn[j]);
#pragma unroll
                for (int i2 = 0; i2 < 4; i2++)
                    fma2(acc2[i2][j], a2[i2], b2);
            }
        }
        __syncthreads();
    }

    // Epilogue: add bias, scatter to [B,H,S,D]
#pragma unroll
    for (int i2 = 0; i2 < 4; i2++) {
#pragma unroll
        for (int j = 0; j < 8; j++) {
            float lo, hi;
            upk2(lo, hi, acc2[i2][j]);
            int n = n0 + tx * 8 + j;
            int h = n >> 6;
            int d = n & 63;
            {
                int m = m0 + ty * 8 + i2 * 2;
                int b = m >> 10, s = m & 1023;
                outp[(((size_t)(b * Hc + h)) * Sc + s) * Dc + d] = lo + bias[n];
            }
            {
                int m = m0 + ty * 8 + i2 * 2 + 1;
                int b = m >> 10, s = m & 1023;
                outp[(((size_t)(b * Hc + h)) * Sc + s) * Dc + d] = hi + bias[n];
            }
        }
    }
}

// ---------------------------------------------------------------------------
// Kernel B: fused attention, 128-query x 64-key tiles, 8x4 micro-tile,
// f32x2 d-packed score FMAs, swizzled K/E rows (2-way max conflicts),
// duplicated P pairs for packed PV.
// ---------------------------------------------------------------------------
#define QS 68     // Q row stride (floats)
#define KS 82     // K row stride (+ per-row swizzle)
#define ES 82     // E row stride (+ per-row swizzle)
#define VS 68     // V row stride
#define PS 130    // P row stride (64 dup-pairs + pad)

#define QOFF  0                    // 128 x 68        = 8704
#define KOFF  8704                 // 64 x 82 + 16    = 5264
#define VOFF  13968                // 64 x 68         = 4352
#define EOFF  18320                // 191 x 82 + 16   = 15680
#define POFF  34000                // 128 x 130       = 16640
#define DNOFF 50640                // 128
#define AMOFF 50768                // 64
#define SKOFF 50832                // 64
#define SMEMF 50896
#define ATTN_SMEM_BYTES (SMEMF * 4)   // 203584 B

__global__ __launch_bounds__(256, 1) void attn_kernel(const float* __restrict__ attn_mask,
                                                      const int*   __restrict__ skim,
                                                      const float* __restrict__ dist_emb,
                                                      float*       __restrict__ out)
{
    extern __shared__ float smf[];
    const int tid = threadIdx.x;
    const int l0  = blockIdx.x * 128;
    const int bh  = blockIdx.y;
    const int b   = bh >> 4;
    const int h   = bh & 15;
    const int ty  = tid >> 4;   // 0..15 -> 8 query rows each
    const int tx  = tid & 15;   // 0..15 -> 4 key cols each

    const float* q = g_q + (size_t)bh * Sc * Dc;
    const float* k = g_k + (size_t)bh * Sc * Dc;
    const float* v = g_v + (size_t)bh * Sc * Dc;

    // Load Q tile (128x64), stride 68 (16B-aligned rows)
#pragma unroll
    for (int i = 0; i < 8; i++) {
        int f   = tid + i * 256;       // 0..2047 float4s
        int row = f >> 4;
        int c4  = (f & 15) << 2;
        float4 val = *(const float4*)(q + (size_t)(l0 + row) * 64 + c4);
        *(float4*)&smf[QOFF + row * QS + c4] = val;
    }
    if (tid < 128) smf[DNOFF + tid] = 0.f;

    ull pv2[8][2];                 // PV acc: pairs along d (dd, dd+1)
#pragma unroll
    for (int i = 0; i < 8; i++) { pv2[i][0] = 0ull; pv2[i][1] = 0ull; }

    const int jb0 = 8 * ty - 4 * tx + 60;        // first diag row (mult of 4)
    int sw[3];
#pragma unroll
    for (int g = 0; g < 3; g++) sw[g] = ((((jb0 >> 2) + g) & 7) << 1);
    const int ebr = EOFF + jb0 * ES;
    const int qb  = QOFF + ty * 8 * QS;
    const int kb  = KOFF + tx * 4 * KS + ((tx & 7) << 1);

    for (int r0 = 0; r0 < Sc; r0 += 64) {
        __syncthreads();   // prior PV done before tiles are overwritten

        // K (swizzled rows) and V
#pragma unroll
        for (int i = 0; i < 4; i++) {
            int f   = tid + i * 256;
            int row = f >> 4;
            int c4  = (f & 15) << 2;
            float4 kv = *(const float4*)(k + (size_t)(r0 + row) * 64 + c4);
            int ka = KOFF + row * KS + (((row >> 2) & 7) << 1) + c4;
            *(float2*)&smf[ka]     = make_float2(kv.x, kv.y);
            *(float2*)&smf[ka + 2] = make_float2(kv.z, kv.w);
            float4 vv = *(const float4*)(v + (size_t)(r0 + row) * 64 + c4);
            *(float4*)&smf[VOFF + row * VS + c4] = vv;
        }
        // E band: rows [l0-r0+960 .. +1150], 191 rows x 64 (swizzled)
        {
            int ebase = l0 - r0 + 960;
#pragma unroll
            for (int i = 0; i < 12; i++) {
                int f = tid + i * 256;
                if (f < 3056) {
                    int row = f >> 4;
                    int c4  = (f & 15) << 2;
                    float4 ev = *(const float4*)(dist_emb + (size_t)(ebase + row) * 64 + c4);
                    int ea = EOFF + row * ES + (((row >> 2) & 7) << 1) + c4;
                    *(float2*)&smf[ea]     = make_float2(ev.x, ev.y);
                    *(float2*)&smf[ea + 2] = make_float2(ev.z, ev.w);
                }
            }
        }
        if (tid < 64) {
            smf[AMOFF + tid] = attn_mask[b * Sc + r0 + tid];
            smf[SKOFF + tid] = (float)skim[b * Sc + r0 + tid];
        }
        __syncthreads();

        // ---- Scores: s[il][ir] = sum_d q*k + sum_d q*e, f32x2 over d-pairs
        ull s2[8][4];
#pragma unroll
        for (int i = 0; i < 8; i++)
#pragma unroll
            for (int j = 0; j < 4; j++) s2[i][j] = 0ull;

#pragma unroll 2
        for (int d2 = 0; d2 < 32; d2++) {
            const int d = d2 << 1;
            ull q2[8], k2[4], e2[11];
#pragma unroll
            for (int il = 0; il < 8; il++)
                q2[il] = *(const ull*)&smf[qb + il * QS + d];
#pragma unroll
            for (int ir = 0; ir < 4; ir++)
                k2[ir] = *(const ull*)&smf[kb + ir * KS + d];
#pragma unroll
            for (int t = 0; t < 11; t++)
                e2[t] = *(const ull*)&smf[ebr + t * ES + sw[t >> 2] + d];
#pragma unroll
            for (int il = 0; il < 8; il++)
#pragma unroll
                for (int ir = 0; ir < 4; ir++) {
                    fma2(s2[il][ir], q2[il], k2[ir]);
                    fma2(s2[il][ir], q2[il], e2[il - ir + 3]);
                }
        }

        // ---- probs: exp(s/8 + am) * skim; write duplicated pairs; denoms
#pragma unroll
        for (int il = 0; il < 8; il++) {
            int l = ty * 8 + il;
            float rs = 0.f;
#pragma unroll
            for (int ir = 0; ir < 4; ir++) {
                float lo, hi;
                upk2(lo, hi, s2[il][ir]);
                float p = __expf((lo + hi) * 0.125f + smf[AMOFF + tx * 4 + ir])
                          * smf[SKOFF + tx * 4 + ir];
                *(ull*)&smf[POFF + l * PS + (tx * 4 + ir) * 2] = pk2(p, p);
                rs += p;
            }
            rs += __shfl_xor_sync(0xffffffffu, rs, 1);
            rs += __shfl_xor_sync(0xffffffffu, rs, 2);
            rs += __shfl_xor_sync(0xffffffffu, rs, 4);
            rs += __shfl_xor_sync(0xffffffffu, rs, 8);
            if (tx == 0) smf[DNOFF + l] += rs;
        }
        __syncwarp();   // P rows for this warp's ty-pair fully written

        // ---- PV: acc2[il][dd2] += P_dup * (v[dd], v[dd+1])
#pragma unroll 4
        for (int rr = 0; rr < 64; rr++) {
            ull v0 = *(const ull*)&smf[VOFF + rr * VS + tx * 4];
            ull v1 = *(const ull*)&smf[VOFF + rr * VS + tx * 4 + 2];
#pragma unroll
            for (int il = 0; il < 8; il++) {
                ull p2 = *(const ull*)&smf[POFF + (ty * 8 + il) * PS + rr * 2];
                fma2(pv2[il][0], p2, v0);
                fma2(pv2[il][1], p2, v1);
            }
        }
    }
    __syncwarp();

    // ---- write out: out[b, l, h*64 + d] = acc / (eps + denom)
#pragma unroll
    for (int il = 0; il < 8; il++) {
        int l = l0 + ty * 8 + il;
        float dinv = 1.f / (1e-8f + smf[DNOFF + ty * 8 + il]);
        float a0, a1, a2_, a3;
        upk2(a0, a1, pv2[il][0]);
        upk2(a2_, a3, pv2[il][1]);
        float4 o = make_float4(a0 * dinv, a1 * dinv, a2_ * dinv, a3 * dinv);
        *(float4*)&out[((size_t)(b * Sc + l)) * HIDc + h * 64 + tx * 4] = o;
    }
}

// ---------------------------------------------------------------------------
extern "C" void kernel_launch(void* const* d_in, const int* in_sizes, int n_in,
                              void* d_out, int out_size)
{
    const float* hidden = (const float*)d_in[0];
    const float* amask  = (const float*)d_in[1];
    const int*   skim   = (const int*)  d_in[2];
    const float* Wq     = (const float*)d_in[3];
    const float* bq     = (const float*)d_in[4];
    const float* Wk     = (const float*)d_in[5];
    const float* bk     = (const float*)d_in[6];
    const float* Wv     = (const float*)d_in[7];
    const float* bv     = (const float*)d_in[8];
    const float* demb   = (const float*)d_in[9];
    float* out = (float*)d_out;

    dim3 ggrid(8, 32);   // N/128, M/128
    gemm_proj<<<ggrid, 256>>>(hidden, Wq, bq, 0);
    gemm_proj<<<ggrid, 256>>>(hidden, Wk, bk, 1);
    gemm_proj<<<ggrid, 256>>>(hidden, Wv, bv, 2);

    cudaFuncSetAttribute(attn_kernel,
                         cudaFuncAttributeMaxDynamicSharedMemorySize,
                         ATTN_SMEM_BYTES);
    dim3 agrid(Sc / 128, Bc * Hc);
    attn_kernel<<<agrid, 256, ATTN_SMEM_BYTES>>>(amask, skim, demb, out);
}